// round 9
// baseline (speedup 1.0000x reference)
#include <cuda_runtime.h>
#include <cuda_fp16.h>
#include <cstdint>

#define BROWS 4096
#define INF   1024
#define OUTF  1024
#define KDIM  9216          // INF * 9  (silu + 8 basis columns per input feature)

// GEMM config: persistent, 128x64 tiles, split-K=4, dynamic queue
#define TMd 128
#define TNd 64
#define KSPLIT 4
#define KPER  (KDIM / KSPLIT)   // 2304
#define CHUNK 64                // k-chunk in halfs
#define ITERSU (KPER / CHUNK)   // 36
#define STAGES 3
#define SROW_H 72               // smem row stride in halfs (144 B, conflict-free)
#define A_BYTES (TMd * SROW_H * 2)        // 18432
#define B_BYTES (TNd * SROW_H * 2)        // 9216
#define STAGE_BYTES (A_BYTES + B_BYTES)   // 27648
#define SMEM_TOTAL (STAGES * STAGE_BYTES + 16)  // 82960
#define NTILES ((BROWS / TMd) * (OUTF / TNd))           // 512
#define NUNITS (NTILES * KSPLIT)                        // 2048
#define GCTAS 296
#define GTHREADS 128

// Scratch (static device globals — no runtime allocation)
__device__ __align__(256) __half g_act[(size_t)BROWS * KDIM];   // 75 MB
__device__ __align__(256) __half g_w[(size_t)OUTF * KDIM];      // 19 MB
__device__ __align__(256) float  g_part[(size_t)KSPLIT * BROWS * OUTF];  // 67 MB
__device__ int g_ctr;
__device__ int g_tcnt[NTILES];

// ---------------------------------------------------------------------------
// Kernel 1 (merged prep):
//  blocks [0, 2048): activation matrix — closed-form uniform cubic B-spline.
//    Act[b, i*9+0]=silu(x); only 4 basis cols (q=j-3..j) are nonzero.
//  blocks [2048, 6144): weight interleave W[o, i*9+0]=bw, [..+1+q]=sw[o,i,q].
//  block 2048 also resets the GEMM work queue + per-tile counters.
// ---------------------------------------------------------------------------
#define ACT_EPT 8
#define ACT_BLOCKS ((BROWS * INF) / (256 * ACT_EPT))   // 2048
#define W_BLOCKS   ((OUTF * INF) / 256)                // 4096

__global__ __launch_bounds__(256) void prep_kernel(const float* __restrict__ x,
                                                   const float* __restrict__ grid,
                                                   const float* __restrict__ bw,
                                                   const float* __restrict__ sw) {
    __shared__ __half sbuf[256 * ACT_EPT * 9];
    const int tid = threadIdx.x;
    const int bid = blockIdx.x;

    if (bid < ACT_BLOCKS) {
        const size_t base = (size_t)bid * (256 * ACT_EPT);
        const float g0   = __ldg(grid);
        const float invh = 11.f / (__ldg(grid + 11) - g0);

        // phase 1: zero-fill the staging tile (vectorized)
        uint4 z; z.x = z.y = z.z = z.w = 0u;
#pragma unroll
        for (int i = 0; i < 9; i++) ((uint4*)sbuf)[tid + i * 256] = z;
        __syncthreads();

        // phase 2: compute + scatter the 5 nonzero halfs per element
#pragma unroll
        for (int e = 0; e < ACT_EPT; e++) {
            const int loc = tid + e * 256;
            float xv = x[base + loc];

            float u = (xv - g0) * invh;
            float jf = floorf(u);
            int j = (int)jf;
            j = j < 0 ? 0 : (j > 10 ? 10 : j);
            float f = u - (float)j;
            float f2 = f * f, f3 = f2 * f;
            float om = 1.f - f;
            float p0 = f3 * (1.f / 6.f);                 // basis q = j
            float p3 = om * om * om * (1.f / 6.f);       // basis q = j-3
            float p2 = 0.5f * f3 - f2 + (4.f / 6.f);     // basis q = j-2
            float p1 = 1.f - p0 - p2 - p3;               // basis q = j-1

            float s = xv * __frcp_rn(1.f + __expf(-xv)); // silu

            __half* o = sbuf + loc * 9;
            o[0] = __float2half_rn(s);
            if (j < 8)               o[1 + j]     = __float2half_rn(p0);
            if (j >= 1 && j - 1 < 8) o[1 + j - 1] = __float2half_rn(p1);
            if (j >= 2 && j - 2 < 8) o[1 + j - 2] = __float2half_rn(p2);
            if (j >= 3 && j - 3 < 8) o[1 + j - 3] = __float2half_rn(p3);
        }
        __syncthreads();

        const uint4* s4 = (const uint4*)sbuf;            // 2304 x 16B
        uint4* g4 = (uint4*)(g_act + base * 9);
#pragma unroll
        for (int i = tid; i < 2304; i += 256) g4[i] = s4[i];
    } else {
        const int wb = bid - ACT_BLOCKS;
        if (wb == 0) {
            if (tid == 0) g_ctr = 0;
            if (tid < NTILES) g_tcnt[tid] = 0;
            if (tid + 256 < NTILES) g_tcnt[tid + 256] = 0;
        }
        int idx = wb * 256 + tid;   // o*1024 + i
        __half* o = sbuf + tid * 9;
        o[0] = __float2half_rn(bw[idx]);
        const float4* sp = (const float4*)(sw + (size_t)idx * 8);
        float4 a = sp[0], b = sp[1];
        o[1] = __float2half_rn(a.x); o[2] = __float2half_rn(a.y);
        o[3] = __float2half_rn(a.z); o[4] = __float2half_rn(a.w);
        o[5] = __float2half_rn(b.x); o[6] = __float2half_rn(b.y);
        o[7] = __float2half_rn(b.z); o[8] = __float2half_rn(b.w);
        __syncthreads();

        const uint4* s4 = (const uint4*)sbuf;
        uint4* g4 = (uint4*)(g_w + (size_t)wb * 2304);
#pragma unroll
        for (int i = tid; i < 288; i += 256) g4[i] = s4[i];
    }
}

// ---------------------------------------------------------------------------
// Kernel 2: fp16 mma.sync GEMM, persistent split-K, fused reduction.
// 296 CTAs (2/SM), 2048 units (32m x 4k x 16n), 4 warps (2x2), warp 64x32.
// Last split-K finisher per tile sums the 4 partial planes -> out.
// ---------------------------------------------------------------------------
__device__ __forceinline__ void issue_stage(uint32_t sb, int stage, int it,
                                            int m0, int n0, int kb0, int tid) {
    const int kk = kb0 + it * CHUNK;
    const uint32_t sA = sb + stage * STAGE_BYTES;
    const uint32_t sB = sA + A_BYTES;
#pragma unroll
    for (int j = 0; j < 12; j++) {            // 192 rows x 8 chunks = 1536 copies
        int id  = tid + j * GTHREADS;         // 0..1535
        int row = id >> 3, c = id & 7;
        if (row < TMd) {
            const __half* ga = &g_act[(size_t)(m0 + row) * KDIM + kk + c * 8];
            asm volatile("cp.async.cg.shared.global [%0], [%1], 16;"
                         :: "r"(sA + (uint32_t)(row * SROW_H + c * 8) * 2), "l"(ga));
        } else {
            int r2 = row - TMd;
            const __half* gb = &g_w[(size_t)(n0 + r2) * KDIM + kk + c * 8];
            asm volatile("cp.async.cg.shared.global [%0], [%1], 16;"
                         :: "r"(sB + (uint32_t)(r2 * SROW_H + c * 8) * 2), "l"(gb));
        }
    }
}

__global__ __launch_bounds__(GTHREADS, 2) void gemm_kernel(float* __restrict__ out) {
    extern __shared__ __align__(16) char smem[];
    const uint32_t sb = (uint32_t)__cvta_generic_to_shared(smem);
    int* s_unit = (int*)(smem + STAGES * STAGE_BYTES);
    int* s_old  = s_unit + 1;
    const int tid = threadIdx.x;
    const int wid = tid >> 5, lane = tid & 31;
    const int g = lane >> 2, t = lane & 3;
    const int wm = wid >> 1, wn = wid & 1;     // 2 x 2 warp grid

    for (;;) {
        if (tid == 0) *s_unit = atomicAdd(&g_ctr, 1);
        __syncthreads();
        const int u = *s_unit;
        if (u >= NUNITS) break;
        const int mi0 = u >> 6;                 // 16 consecutive units share A strip
        const int m0  = mi0 * TMd;
        const int ks  = (u >> 4) & 3;
        const int ni0 = u & 15;
        const int n0  = ni0 * TNd;
        const int kb0 = ks * KPER;
        const int tile = mi0 * 16 + ni0;

        float acc[4][4][4];
#pragma unroll
        for (int i = 0; i < 4; i++)
#pragma unroll
            for (int jj = 0; jj < 4; jj++)
#pragma unroll
                for (int r = 0; r < 4; r++) acc[i][jj][r] = 0.f;

#pragma unroll
        for (int s = 0; s < STAGES - 1; s++) {
            issue_stage(sb, s, s, m0, n0, kb0, tid);
            asm volatile("cp.async.commit_group;");
        }

        const int aRow = wm * 64 + g;
        const int bRow = wn * 32 + g;

        for (int it = 0; it < ITERSU; ++it) {
            asm volatile("cp.async.wait_group %0;" :: "n"(STAGES - 2));
            __syncthreads();
            if (it + STAGES - 1 < ITERSU)
                issue_stage(sb, (it + STAGES - 1) % STAGES, it + STAGES - 1,
                            m0, n0, kb0, tid);
            asm volatile("cp.async.commit_group;");

            const int buf = it % STAGES;
            const __half* As = (const __half*)(smem + buf * STAGE_BYTES);
            const __half* Bs = (const __half*)(smem + buf * STAGE_BYTES + A_BYTES);

#pragma unroll
            for (int kb = 0; kb < CHUNK; kb += 16) {
                uint32_t af[4][4], bf[4][2];
#pragma unroll
                for (int mi = 0; mi < 4; mi++) {
                    int r = aRow + mi * 16;
                    af[mi][0] = *(const uint32_t*)&As[r * SROW_H + kb + 2 * t];
                    af[mi][1] = *(const uint32_t*)&As[(r + 8) * SROW_H + kb + 2 * t];
                    af[mi][2] = *(const uint32_t*)&As[r * SROW_H + kb + 2 * t + 8];
                    af[mi][3] = *(const uint32_t*)&As[(r + 8) * SROW_H + kb + 2 * t + 8];
                }
#pragma unroll
                for (int ni = 0; ni < 4; ni++) {
                    int r = bRow + ni * 8;
                    bf[ni][0] = *(const uint32_t*)&Bs[r * SROW_H + kb + 2 * t];
                    bf[ni][1] = *(const uint32_t*)&Bs[r * SROW_H + kb + 2 * t + 8];
                }
#pragma unroll
                for (int mi = 0; mi < 4; mi++)
#pragma unroll
                    for (int ni = 0; ni < 4; ni++) {
                        asm volatile(
                            "mma.sync.aligned.m16n8k16.row.col.f32.f16.f16.f32 "
                            "{%0,%1,%2,%3}, {%4,%5,%6,%7}, {%8,%9}, {%0,%1,%2,%3};"
                            : "+f"(acc[mi][ni][0]), "+f"(acc[mi][ni][1]),
                              "+f"(acc[mi][ni][2]), "+f"(acc[mi][ni][3])
                            : "r"(af[mi][0]), "r"(af[mi][1]),
                              "r"(af[mi][2]), "r"(af[mi][3]),
                              "r"(bf[ni][0]), "r"(bf[ni][1]));
                    }
            }
        }

        // Epilogue: write partial tile to g_part[ks]
        float* part = g_part + (size_t)ks * BROWS * OUTF;
#pragma unroll
        for (int mi = 0; mi < 4; mi++)
#pragma unroll
            for (int ni = 0; ni < 4; ni++) {
                int row = m0 + wm * 64 + mi * 16 + g;
                int col = n0 + wn * 32 + ni * 8 + 2 * t;
                float2 v0 = make_float2(acc[mi][ni][0], acc[mi][ni][1]);
                float2 v1 = make_float2(acc[mi][ni][2], acc[mi][ni][3]);
                *(float2*)&part[(size_t)row * OUTF + col]       = v0;
                *(float2*)&part[(size_t)(row + 8) * OUTF + col] = v1;
            }

        // Fused split-K reduction: 4th arrival sums the 4 planes.
        __threadfence();
        __syncthreads();
        if (tid == 0) *s_old = atomicAdd(&g_tcnt[tile], 1);
        __syncthreads();
        if (*s_old == 3) {
            __threadfence();
            const float4* p0 = (const float4*)g_part;
            const float4* p1 = p0 + ((size_t)BROWS * OUTF) / 4;
            const float4* p2 = p1 + ((size_t)BROWS * OUTF) / 4;
            const float4* p3 = p2 + ((size_t)BROWS * OUTF) / 4;
            float4* o4 = (float4*)out;
#pragma unroll
            for (int i = tid; i < (TMd * TNd) / 4; i += GTHREADS) {
                int r = i >> 4, c4 = i & 15;              // 16 float4 per tile row
                size_t off = (((size_t)(m0 + r) * OUTF + n0) >> 2) + c4;
                float4 a = p0[off], b = p1[off], c = p2[off], d = p3[off];
                float4 rr;
                rr.x = (a.x + b.x) + (c.x + d.x);
                rr.y = (a.y + b.y) + (c.y + d.y);
                rr.z = (a.z + b.z) + (c.z + d.z);
                rr.w = (a.w + b.w) + (c.w + d.w);
                o4[off] = rr;
            }
        }
        // next-unit barrier protects smem stage reuse
    }
}

// ---------------------------------------------------------------------------
extern "C" void kernel_launch(void* const* d_in, const int* in_sizes, int n_in,
                              void* d_out, int out_size) {
    const float* x    = (const float*)d_in[0];
    const float* bw   = (const float*)d_in[1];
    const float* sw   = (const float*)d_in[2];
    const float* grid = (const float*)d_in[3];
    float* out = (float*)d_out;

    cudaFuncSetAttribute(gemm_kernel, cudaFuncAttributeMaxDynamicSharedMemorySize,
                         SMEM_TOTAL);

    prep_kernel<<<ACT_BLOCKS + W_BLOCKS, 256>>>(x, grid, bw, sw);
    gemm_kernel<<<GCTAS, GTHREADS, SMEM_TOTAL>>>(out);
}